// round 16
// baseline (speedup 1.0000x reference)
#include <cuda_runtime.h>
#include <cuda_fp16.h>
#include <cstdint>

// EdgeNetwork via single-piece fp16 mma.sync m16n8k16.
// H = E@W + b ; messages[g,i] = sum_j relu(H[g, 32i+j]) * s[g,j]
// E, W rounded to fp16 (rel err ~3e-4 << 1e-3); accum + epilogue fp32.
// R16: R14 base + uint4 A-fragment loads (EH2[hp][g][q]), float4 s loads
// (SPN[row][q][a][sel], scalar use), hp loop unroll 2.

#define NTHREADS 256

// dynamic smem offsets (bytes)
#define SM_EH   0                        // uint4[256]           4 KB  EH2[hp][g][q]
#define SM_SP   4096                     // float[4096]         16 KB  SPN[row][q][a][sel]
#define SM_OSM  20480                    // float[128*68]    34816 B
#define SM_TOTAL (20480 + 34816)         // 55296 B/CTA (x3 = 162 KB/SM)

// fp16 W, fragment-permuted:
// d_Wh[n*4+q] = { h2(w[2q][n],w[2q+1][n]), h2(w[2q+8][n],w[2q+9][n]) }
__device__ uint2 d_Wh[4096];

__device__ __forceinline__ uint32_t pack_h2f(float a, float b) {
    __half2 h = __floats2half2_rn(a, b);
    return *reinterpret_cast<uint32_t*>(&h);
}

__global__ void prep_w(const float* __restrict__ W) {
    int idx = blockIdx.x * 256 + threadIdx.x;   // 0..4095 over [n][q]
    int n = idx >> 2, q = idx & 3;
    d_Wh[idx] = make_uint2(
        pack_h2f(W[(2 * q)     * 1024 + n], W[(2 * q + 1) * 1024 + n]),
        pack_h2f(W[(2 * q + 8) * 1024 + n], W[(2 * q + 9) * 1024 + n]));
}

// D = A*B + {cx,cy,cx,cy}
__device__ __forceinline__ void mma16c(float* d, uint32_t a0, uint32_t a1,
                                       uint32_t a2, uint32_t a3,
                                       uint32_t b0, uint32_t b1,
                                       float cx, float cy) {
    asm volatile(
        "mma.sync.aligned.m16n8k16.row.col.f32.f16.f16.f32 "
        "{%0,%1,%2,%3}, {%4,%5,%6,%7}, {%8,%9}, {%10,%11,%10,%11};"
        : "=f"(d[0]), "=f"(d[1]), "=f"(d[2]), "=f"(d[3])
        : "r"(a0), "r"(a1), "r"(a2), "r"(a3), "r"(b0), "r"(b1),
          "f"(cx), "f"(cy));
}

__global__ __launch_bounds__(NTHREADS, 3) void edge_net_mma(
    const float* __restrict__ states,
    const float* __restrict__ edges,
    const float* __restrict__ bg,
    float* __restrict__ out)
{
    extern __shared__ char sm[];
    uint4* EH2 = (uint4*)(sm + SM_EH);       // [hp][g][q]: .xy rows hp*16+g, .zw +8
    float* SPN = (float*)(sm + SM_SP);       // row*32 + q*8 + a*2 + sel
    float* OSM = (float*)(sm + SM_OSM);      // [row][il][q], pitch 68

    const int tid = threadIdx.x;
    const int eb = blockIdx.x & 511;         // edge block (128 edges)
    const int cb = blockIdx.x >> 9;          // column half (512 cols)
    const int gbase = eb * 128;
    const int col0 = cb * 512;

    const int w = tid >> 5, lane = tid & 31;
    const int g = lane >> 2;                 // groupID: row-in-tile / B-col
    const int q = lane & 3;                  // threadID-in-group

    // ---- Stage edges as fp16 fragments into EH2 ----
    {
        const float2* er = (const float2*)(edges + (size_t)gbase * 16);
        #pragma unroll
        for (int k = 0; k < 2; k++) {
            int item = tid + k * 256;        // 0..511 over [row][q]
            int row = item >> 2, qq = item & 3;
            float2 v0 = er[row * 8 + qq];
            float2 v1 = er[row * 8 + qq + 4];
            uint2 frag = make_uint2(pack_h2f(v0.x, v0.y), pack_h2f(v1.x, v1.y));
            int hp = row >> 4, r8 = row & 15;
            int half = r8 >> 3, gg = r8 & 7;
            ((uint2*)EH2)[(hp * 32 + gg * 4 + qq) * 2 + half] = frag;
        }
    }
    // ---- Stage states: SPN[row*32 + q*8 + a*2 + sel] = s[row][8a+2q+sel] ----
    {
        const float4* sv = (const float4*)(states + (size_t)gbase * 32);
        #pragma unroll
        for (int k = 0; k < 4; k++) {
            int idx = tid + k * 256;         // 0..1023 over [row][f4]
            int row = idx >> 3, f4 = idx & 7;
            float4 v = sv[idx];
            int base = row * 32 + (f4 & 1) * 16 + (f4 >> 1) * 2;
            *(float2*)(SPN + base)     = make_float2(v.x, v.y);
            *(float2*)(SPN + base + 8) = make_float2(v.z, v.w);
        }
    }
    __syncthreads();

    // ---- W + bias fragments -> registers (after sync) ----
    uint2 wh[8];
    float2 b2[8];
    #pragma unroll
    for (int ct = 0; ct < 8; ct++) {
        int n = col0 + w * 64 + ct * 8 + g;
        wh[ct] = d_Wh[n * 4 + q];
        b2[ct] = *(const float2*)(bg + col0 + w * 64 + ct * 8 + 2 * q);
    }

    // ---- Main: 8 steps of 16 rows, unroll 2 ----
    #pragma unroll 2
    for (int hp = 0; hp < 8; hp++) {
        const int rb = hp * 16;

        const uint4 aF = EH2[hp * 32 + g * 4 + q];   // .xy rows rb+g, .zw rows rb+8+g

        // s for this thread, both rows, all 4 a-groups
        const float* sp0 = SPN + (rb + g) * 32 + q * 8;
        const float* sp1 = SPN + (rb + 8 + g) * 32 + q * 8;
        const float4 s0lo = *(const float4*)(sp0);       // a=0 (.x,.y), a=1 (.z,.w)
        const float4 s0hi = *(const float4*)(sp0 + 4);   // a=2, a=3
        const float4 s1lo = *(const float4*)(sp1);
        const float4 s1hi = *(const float4*)(sp1 + 4);
        const float sA[8] = { s0lo.x, s0lo.y, s0lo.z, s0lo.w,
                              s0hi.x, s0hi.y, s0hi.z, s0hi.w };
        const float sB[8] = { s1lo.x, s1lo.y, s1lo.z, s1lo.w,
                              s1hi.x, s1hi.y, s1hi.z, s1hi.w };

        float mm[2][2] = {{0.f, 0.f}, {0.f, 0.f}};    // [ip][row-half]

        #pragma unroll
        for (int a = 0; a < 4; a++) {
            #pragma unroll
            for (int ip = 0; ip < 2; ip++) {
                const int ct = ip * 4 + a;
                float d[4];
                mma16c(d, aF.x, aF.z, aF.y, aF.w, wh[ct].x, wh[ct].y,
                       b2[ct].x, b2[ct].y);

                mm[ip][0] = fmaf(fmaxf(d[0], 0.f), sA[2 * a],     mm[ip][0]);
                mm[ip][0] = fmaf(fmaxf(d[1], 0.f), sA[2 * a + 1], mm[ip][0]);
                mm[ip][1] = fmaf(fmaxf(d[2], 0.f), sB[2 * a],     mm[ip][1]);
                mm[ip][1] = fmaf(fmaxf(d[3], 0.f), sB[2 * a + 1], mm[ip][1]);
            }
        }

        // ---- Store quad partials (conflict-free: bank = 4g+q) ----
        #pragma unroll
        for (int ip = 0; ip < 2; ip++) {
            const int il = w * 2 + ip;       // local column 0..15
            OSM[(rb + g) * 68 + il * 4 + q]     = mm[ip][0];
            OSM[(rb + 8 + g) * 68 + il * 4 + q] = mm[ip][1];
        }
    }

    // ---- Flush: sum 4 partials per output, coalesced STG ----
    __syncthreads();
    #pragma unroll
    for (int k = 0; k < 8; k++) {
        int idx = tid + k * 256;             // 0..2047 over [row][il]
        int row = idx >> 4, il = idx & 15;
        float4 p = *(const float4*)(OSM + row * 68 + il * 4);
        out[(size_t)(gbase + row) * 32 + cb * 16 + il] =
            (p.x + p.y) + (p.z + p.w);
    }
}

extern "C" void kernel_launch(void* const* d_in, const int* in_sizes, int n_in,
                              void* d_out, int out_size)
{
    const float* states = (const float*)d_in[0];  // [16, 4096, 32]
    const float* edges  = (const float*)d_in[1];  // [16, 4096, 16]
    const float* W      = (const float*)d_in[2];  // [16, 1024]
    const float* b      = (const float*)d_in[3];  // [1024]
    float* out          = (float*)d_out;          // [16, 4096, 32]

    (void)in_sizes; (void)n_in; (void)out_size;

    static int configured = 0;
    if (!configured) {
        cudaFuncSetAttribute(edge_net_mma,
                             cudaFuncAttributeMaxDynamicSharedMemorySize, SM_TOTAL);
        configured = 1;
    }
    prep_w<<<16, 256>>>(W);
    edge_net_mma<<<1024, NTHREADS, SM_TOTAL>>>(states, edges, b, out);
}